// round 12
// baseline (speedup 1.0000x reference)
#include <cuda_runtime.h>
#include <mma.h>
#include <math.h>

using namespace nvcuda;

#define MAXN (1 << 21)
#define EBLK 128          // encoder threads/block
#define NW 10             // MLP warps per block
#define MBLK (NW * 32)    // MLP threads/block
#define LDA 68            // activation row stride (floats)

typedef unsigned long long u64;

// 256 MB scratch: enc features, chunked float4 layout [8][MAXN]
__device__ float4 g_enc4[8 * MAXN];

// ---- packed f32x2 helpers ----
__device__ __forceinline__ u64 pack2(float lo, float hi) {
    u64 r; asm("mov.b64 %0,{%1,%2};" : "=l"(r) : "f"(lo), "f"(hi)); return r;
}
__device__ __forceinline__ u64 fma2(u64 a, u64 b, u64 c) {
    u64 d; asm("fma.rn.f32x2 %0,%1,%2,%3;" : "=l"(d) : "l"(a), "l"(b), "l"(c));
    return d;
}
__device__ __forceinline__ u64 mul2(u64 a, u64 b) {
    u64 d; asm("mul.rn.f32x2 %0,%1,%2;" : "=l"(d) : "l"(a), "l"(b));
    return d;
}

// ======================================================================
// Kernel 1: hash-grid encoder (pure gather, high occupancy)
// ======================================================================
__global__ __launch_bounds__(EBLK, 5)
void nerf_encode_kernel(const float* __restrict__ xyz,
                        const float* __restrict__ table, int N)
{
    int p = blockIdx.x * EBLK + threadIdx.x;
    if (p >= N) return;

    float x = xyz[3 * p + 0];
    float y = xyz[3 * p + 1];
    float z = xyz[3 * p + 2];

    float enc[32];
    const int res_tab[16] = {16, 22, 30, 42, 58, 80, 111, 153,
                             212, 294, 406, 561, 775, 1072, 1481, 2047};

    #pragma unroll
    for (int l = 0; l < 16; l++) {
        const int res = res_tab[l];
        float px = x * (float)res, py = y * (float)res, pz = z * (float)res;
        float fx = floorf(px), fy = floorf(py), fz = floorf(pz);
        float wx = px - fx, wy = py - fy, wz = pz - fz;
        unsigned ix = (unsigned)fx, iy = (unsigned)fy, iz = (unsigned)fz;

        unsigned i0, i1, i2, i3, i4, i5, i6, i7;
        if (res <= 79) {  // dense level: (res+1)^3 <= 2^19
            unsigned s = (unsigned)(res + 1);
            unsigned ss = s * s;
            unsigned base = ix + iy * s + iz * ss;
            i0 = base;      i1 = base + 1;
            i2 = base + s;  i3 = base + s + 1;
            i4 = base + ss; i5 = i4 + 1;
            i6 = i4 + s;    i7 = i4 + s + 1;
        } else {          // hashed level
            const unsigned P1 = 2654435761u, P2 = 805459861u;
            const unsigned m = (1u << 19) - 1u;
            unsigned hx0 = ix, hx1 = ix + 1u;
            unsigned hy0 = iy * P1, hy1 = hy0 + P1;
            unsigned hz0 = iz * P2, hz1 = hz0 + P2;
            i0 = (hx0 ^ hy0 ^ hz0) & m; i1 = (hx1 ^ hy0 ^ hz0) & m;
            i2 = (hx0 ^ hy1 ^ hz0) & m; i3 = (hx1 ^ hy1 ^ hz0) & m;
            i4 = (hx0 ^ hy0 ^ hz1) & m; i5 = (hx1 ^ hy0 ^ hz1) & m;
            i6 = (hx0 ^ hy1 ^ hz1) & m; i7 = (hx1 ^ hy1 ^ hz1) & m;
        }

        const u64* tl = reinterpret_cast<const u64*>(table) + ((size_t)l << 19);
        u64 f0 = __ldg(tl + i0); u64 f1 = __ldg(tl + i1);
        u64 f2 = __ldg(tl + i2); u64 f3 = __ldg(tl + i3);
        u64 f4 = __ldg(tl + i4); u64 f5 = __ldg(tl + i5);
        u64 f6 = __ldg(tl + i6); u64 f7 = __ldg(tl + i7);

        float ox = 1.0f - wx, oy = 1.0f - wy, oz = 1.0f - wz;
        u64 wxp = pack2(wx, wx), oxp = pack2(ox, ox);
        u64 wyp = pack2(wy, wy), oyp = pack2(oy, oy);
        u64 wzp = pack2(wz, wz), ozp = pack2(oz, oz);

        u64 a0 = fma2(f1, wxp, mul2(f0, oxp));
        u64 a1 = fma2(f3, wxp, mul2(f2, oxp));
        u64 a2 = fma2(f5, wxp, mul2(f4, oxp));
        u64 a3 = fma2(f7, wxp, mul2(f6, oxp));
        u64 c0 = fma2(a1, wyp, mul2(a0, oyp));
        u64 c1 = fma2(a3, wyp, mul2(a2, oyp));
        u64 e  = fma2(c1, wzp, mul2(c0, ozp));
        *reinterpret_cast<u64*>(enc + 2 * l) = e;
    }

    #pragma unroll
    for (int c = 0; c < 8; c++) {
        float4 v = make_float4(enc[4 * c + 0], enc[4 * c + 1],
                               enc[4 * c + 2], enc[4 * c + 3]);
        g_enc4[c * MAXN + p] = v;   // coalesced STG.128
    }
}

// ======================================================================
// Kernel 2: MLPs via wmma tf32 (warp-local, hi/lo split on activations)
// ======================================================================
template <class Frag>
__device__ __forceinline__ void to_tf32(Frag& f) {
    #pragma unroll
    for (int i = 0; i < f.num_elements; i++)
        f.x[i] = wmma::__float_to_tf32(f.x[i]);
}

// C[32][16*NT] = [relu](A[32][8*KT] @ B), warp-local (r0 = 0 in warp buffer).
// A activations split hi/lo (2 mmas per B fragment) for near-fp32 accuracy.
template <int KT, int NT, bool RELU>
__device__ __forceinline__ void mlp_layer(const float* A, const float* B,
                                          int ldb, float* C)
{
    #pragma unroll
    for (int m = 0; m < 2; m++) {
        wmma::fragment<wmma::matrix_a, 16, 16, 8, wmma::precision::tf32,
                       wmma::row_major> ah[KT], al[KT];
        #pragma unroll
        for (int k = 0; k < KT; k++) {
            wmma::load_matrix_sync(ah[k], A + 16 * m * LDA + 8 * k, LDA);
            #pragma unroll
            for (int i = 0; i < ah[k].num_elements; i++) {
                float v = ah[k].x[i];
                float vh = wmma::__float_to_tf32(v);
                ah[k].x[i] = vh;
                al[k].x[i] = wmma::__float_to_tf32(v - vh);
            }
        }
        #pragma unroll
        for (int n = 0; n < NT; n++) {
            wmma::fragment<wmma::accumulator, 16, 16, 8, float> c;
            wmma::fill_fragment(c, 0.0f);
            #pragma unroll
            for (int k = 0; k < KT; k++) {
                wmma::fragment<wmma::matrix_b, 16, 16, 8, wmma::precision::tf32,
                               wmma::row_major> b;
                wmma::load_matrix_sync(b, B + 8 * k * ldb + 16 * n, ldb);
                to_tf32(b);
                wmma::mma_sync(c, al[k], b, c);
                wmma::mma_sync(c, ah[k], b, c);
            }
            if (RELU) {
                #pragma unroll
                for (int i = 0; i < c.num_elements; i++)
                    c.x[i] = fmaxf(c.x[i], 0.0f);
            }
            wmma::store_matrix_sync(C + 16 * m * LDA + 16 * n, c, LDA,
                                    wmma::mem_row_major);
        }
    }
}

__global__ __launch_bounds__(MBLK, 1)
void nerf_mlp_kernel(const float* __restrict__ dirp,
                     const float* __restrict__ ws1g,
                     const float* __restrict__ ws2g,
                     const float* __restrict__ wr1g,
                     const float* __restrict__ wr2g,
                     const float* __restrict__ wr3g,
                     float* __restrict__ out, int N)
{
    extern __shared__ float smem[];
    // per-warp double activation buffers [NW][2][32][LDA]
    float* sw1  = smem + NW * 2 * 32 * LDA;   // [32][64]
    float* sw2p = sw1 + 32 * 64;              // [64][32] (17 + pad0)
    float* sr1  = sw2p + 64 * 32;             // [32][64]
    float* sr2  = sr1 + 32 * 64;              // [64][64]
    float* sr3p = sr2 + 64 * 64;              // [64][16] (3 + pad0)

    const int t = threadIdx.x;

    for (int i = t; i < 2048; i += MBLK) { sw1[i] = ws1g[i]; sr1[i] = wr1g[i]; }
    for (int i = t; i < 4096; i += MBLK) sr2[i] = wr2g[i];
    for (int i = t; i < 2048; i += MBLK) {
        int k = i >> 5, n = i & 31;
        sw2p[i] = (n < 17) ? ws2g[k * 17 + n] : 0.0f;
    }
    for (int i = t; i < 1024; i += MBLK) {
        int k = i >> 4, n = i & 15;
        sr3p[i] = (n < 3) ? wr3g[k * 3 + n] : 0.0f;
    }
    __syncthreads();

    const int w = t >> 5;
    const int lane = t & 31;
    const int p = blockIdx.x * MBLK + t;
    const bool valid = p < N;

    float* bufA = smem + w * (2 * 32 * LDA);
    float* bufB = bufA + 32 * LDA;
    float* myrow = bufA + lane * LDA;

    // load enc from scratch (coalesced float4 per chunk)
    #pragma unroll
    for (int c = 0; c < 8; c++) {
        float4 v = valid ? g_enc4[c * MAXN + p]
                         : make_float4(0.f, 0.f, 0.f, 0.f);
        *reinterpret_cast<float4*>(myrow + 4 * c) = v;
    }
    __syncwarp();

    // sigma layer 1: enc(32) @ ws1 -> relu -> bufB(64)
    mlp_layer<4, 4, true>(bufA, sw1, 64, bufB);
    __syncwarp();
    // sigma layer 2: bufB(64) @ ws2p -> bufA cols 32..63  (g = cols 32..48)
    mlp_layer<8, 2, false>(bufB, sw2p, 32, bufA + 32);
    __syncwarp();

    // epilogue: sigma out, rgb_in = [SH(dir) | geo_feat]
    if (valid) {
        out[3 * N + p] = fmaxf(myrow[32], 0.0f);

        float dx = dirp[3 * p + 0] * 2.0f - 1.0f;
        float dy = dirp[3 * p + 1] * 2.0f - 1.0f;
        float dz = dirp[3 * p + 2] * 2.0f - 1.0f;
        float x2 = dx * dx, y2 = dy * dy, z2 = dz * dz;
        float xy = dx * dy, yz = dy * dz, xz = dx * dz;

        #pragma unroll
        for (int j = 0; j < 16; j++) myrow[16 + j] = myrow[33 + j];

        myrow[0]  = 0.28209479177387814f;
        myrow[1]  = -0.48860251190291987f * dy;
        myrow[2]  = 0.48860251190291987f * dz;
        myrow[3]  = -0.48860251190291987f * dx;
        myrow[4]  = 1.0925484305920792f * xy;
        myrow[5]  = -1.0925484305920792f * yz;
        myrow[6]  = 0.94617469575756f * z2 - 0.31539156525252f;
        myrow[7]  = -1.0925484305920792f * xz;
        myrow[8]  = 0.5462742152960396f * (x2 - y2);
        myrow[9]  = 0.5900435899266435f * dy * (-3.0f * x2 + y2);
        myrow[10] = 2.890611442640554f * xy * dz;
        myrow[11] = 0.4570457994644657f * dy * (1.0f - 5.0f * z2);
        myrow[12] = 0.3731763325901154f * dz * (5.0f * z2 - 3.0f);
        myrow[13] = 0.4570457994644657f * dx * (1.0f - 5.0f * z2);
        myrow[14] = 1.445305721320277f * dz * (x2 - y2);
        myrow[15] = 0.5900435899266435f * dx * (-x2 + 3.0f * y2);
    } else {
        #pragma unroll
        for (int k = 0; k < 32; k++) myrow[k] = 0.0f;
    }
    __syncwarp();

    // rgb layer 1: bufA(32) @ sr1 -> relu -> bufB(64)
    mlp_layer<4, 4, true>(bufA, sr1, 64, bufB);
    __syncwarp();
    // rgb layer 2: bufB(64) @ sr2 -> relu -> bufA(64)
    mlp_layer<8, 4, true>(bufB, sr2, 64, bufA);
    __syncwarp();
    // rgb layer 3: bufA(64) @ sr3p -> bufB cols 0..15
    mlp_layer<8, 1, false>(bufA, sr3p, 16, bufB);
    __syncwarp();

    if (valid) {
        float a0 = bufB[lane * LDA + 0];
        float a1 = bufB[lane * LDA + 1];
        float a2 = bufB[lane * LDA + 2];
        out[3 * p + 0] = 1.0f / (1.0f + __expf(-a0));
        out[3 * p + 1] = 1.0f / (1.0f + __expf(-a1));
        out[3 * p + 2] = 1.0f / (1.0f + __expf(-a2));
    }
}

extern "C" void kernel_launch(void* const* d_in, const int* in_sizes, int n_in,
                              void* d_out, int out_size)
{
    const float* xyz = (const float*)d_in[0];
    const float* dir = (const float*)d_in[1];
    const float* table = (const float*)d_in[2];
    float* out = (float*)d_out;

    int N = in_sizes[0] / 3;

    size_t smem_bytes = (size_t)(NW * 2 * 32 * LDA + 32 * 64 + 64 * 32 +
                                 32 * 64 + 64 * 64 + 64 * 16) * sizeof(float);
    static bool attr_set = false;
    if (!attr_set) {
        cudaFuncSetAttribute(nerf_mlp_kernel,
                             cudaFuncAttributeMaxDynamicSharedMemorySize,
                             (int)smem_bytes);
        attr_set = true;
    }

    int eblocks = (N + EBLK - 1) / EBLK;
    nerf_encode_kernel<<<eblocks, EBLK>>>(xyz, table, N);

    int mblocks = (N + MBLK - 1) / MBLK;
    nerf_mlp_kernel<<<mblocks, MBLK, smem_bytes>>>(
        dir, (const float*)d_in[3], (const float*)d_in[4],
        (const float*)d_in[5], (const float*)d_in[6],
        (const float*)d_in[7], out, N);
}

// round 16
// speedup vs baseline: 1.0770x; 1.0770x over previous
#include <cuda_runtime.h>
#include <mma.h>
#include <math.h>

using namespace nvcuda;

#define MAXN (1 << 21)
#define EBLK 128            // encoder threads/block
#define MBLK 128            // MLP threads/block (4 warps)
#define SLDA 132            // activation row stride in floats (4*33)

typedef unsigned long long u64;

// 256 MB scratch: enc features, chunked float4 layout [8][MAXN]
__device__ float4 g_enc4[8 * MAXN];
// zero-padded weight copies for 16-wide B tiles
__device__ float g_ws2p[64 * 32];   // [64][32], cols 17.. zero
__device__ float g_wr3p[64 * 16];   // [64][16], cols 3.. zero

// ---- packed f32x2 helpers ----
__device__ __forceinline__ u64 pack2(float lo, float hi) {
    u64 r; asm("mov.b64 %0,{%1,%2};" : "=l"(r) : "f"(lo), "f"(hi)); return r;
}
__device__ __forceinline__ u64 fma2(u64 a, u64 b, u64 c) {
    u64 d; asm("fma.rn.f32x2 %0,%1,%2,%3;" : "=l"(d) : "l"(a), "l"(b), "l"(c));
    return d;
}
__device__ __forceinline__ u64 mul2(u64 a, u64 b) {
    u64 d; asm("mul.rn.f32x2 %0,%1,%2;" : "=l"(d) : "l"(a), "l"(b));
    return d;
}

// ======================================================================
// Kernel 0: pad ws2 / wr3 into 16-col-aligned scratch
// ======================================================================
__global__ void pad_weights_kernel(const float* __restrict__ ws2,
                                   const float* __restrict__ wr3)
{
    int t = blockIdx.x * blockDim.x + threadIdx.x;
    int stride = gridDim.x * blockDim.x;
    for (int i = t; i < 64 * 32; i += stride) {
        int k = i >> 5, n = i & 31;
        g_ws2p[i] = (n < 17) ? ws2[k * 17 + n] : 0.0f;
    }
    for (int i = t; i < 64 * 16; i += stride) {
        int k = i >> 4, n = i & 15;
        g_wr3p[i] = (n < 3) ? wr3[k * 3 + n] : 0.0f;
    }
}

// ======================================================================
// Kernel 1: hash-grid encoder (pure gather, high occupancy)
// ======================================================================
__global__ __launch_bounds__(EBLK, 5)
void nerf_encode_kernel(const float* __restrict__ xyz,
                        const float* __restrict__ table, int N)
{
    int p = blockIdx.x * EBLK + threadIdx.x;
    if (p >= N) return;

    float x = xyz[3 * p + 0];
    float y = xyz[3 * p + 1];
    float z = xyz[3 * p + 2];

    float enc[32];
    const int res_tab[16] = {16, 22, 30, 42, 58, 80, 111, 153,
                             212, 294, 406, 561, 775, 1072, 1481, 2047};

    #pragma unroll
    for (int l = 0; l < 16; l++) {
        const int res = res_tab[l];
        float px = x * (float)res, py = y * (float)res, pz = z * (float)res;
        float fx = floorf(px), fy = floorf(py), fz = floorf(pz);
        float wx = px - fx, wy = py - fy, wz = pz - fz;
        unsigned ix = (unsigned)fx, iy = (unsigned)fy, iz = (unsigned)fz;

        unsigned i0, i1, i2, i3, i4, i5, i6, i7;
        if (res <= 79) {  // dense level: (res+1)^3 <= 2^19
            unsigned s = (unsigned)(res + 1);
            unsigned ss = s * s;
            unsigned base = ix + iy * s + iz * ss;
            i0 = base;      i1 = base + 1;
            i2 = base + s;  i3 = base + s + 1;
            i4 = base + ss; i5 = i4 + 1;
            i6 = i4 + s;    i7 = i4 + s + 1;
        } else {          // hashed level
            const unsigned P1 = 2654435761u, P2 = 805459861u;
            const unsigned m = (1u << 19) - 1u;
            unsigned hx0 = ix, hx1 = ix + 1u;
            unsigned hy0 = iy * P1, hy1 = hy0 + P1;
            unsigned hz0 = iz * P2, hz1 = hz0 + P2;
            i0 = (hx0 ^ hy0 ^ hz0) & m; i1 = (hx1 ^ hy0 ^ hz0) & m;
            i2 = (hx0 ^ hy1 ^ hz0) & m; i3 = (hx1 ^ hy1 ^ hz0) & m;
            i4 = (hx0 ^ hy0 ^ hz1) & m; i5 = (hx1 ^ hy0 ^ hz1) & m;
            i6 = (hx0 ^ hy1 ^ hz1) & m; i7 = (hx1 ^ hy1 ^ hz1) & m;
        }

        const u64* tl = reinterpret_cast<const u64*>(table) + ((size_t)l << 19);
        u64 f0 = __ldg(tl + i0); u64 f1 = __ldg(tl + i1);
        u64 f2 = __ldg(tl + i2); u64 f3 = __ldg(tl + i3);
        u64 f4 = __ldg(tl + i4); u64 f5 = __ldg(tl + i5);
        u64 f6 = __ldg(tl + i6); u64 f7 = __ldg(tl + i7);

        float ox = 1.0f - wx, oy = 1.0f - wy, oz = 1.0f - wz;
        u64 wxp = pack2(wx, wx), oxp = pack2(ox, ox);
        u64 wyp = pack2(wy, wy), oyp = pack2(oy, oy);
        u64 wzp = pack2(wz, wz), ozp = pack2(oz, oz);

        u64 a0 = fma2(f1, wxp, mul2(f0, oxp));
        u64 a1 = fma2(f3, wxp, mul2(f2, oxp));
        u64 a2 = fma2(f5, wxp, mul2(f4, oxp));
        u64 a3 = fma2(f7, wxp, mul2(f6, oxp));
        u64 c0 = fma2(a1, wyp, mul2(a0, oyp));
        u64 c1 = fma2(a3, wyp, mul2(a2, oyp));
        u64 e  = fma2(c1, wzp, mul2(c0, ozp));
        *reinterpret_cast<u64*>(enc + 2 * l) = e;
    }

    #pragma unroll
    for (int c = 0; c < 8; c++) {
        float4 v = make_float4(enc[4 * c + 0], enc[4 * c + 1],
                               enc[4 * c + 2], enc[4 * c + 3]);
        g_enc4[c * MAXN + p] = v;   // coalesced STG.128
    }
}

// ======================================================================
// Kernel 2: MLPs via wmma tf32, warp-local, weights via L1 from global
// ======================================================================
// C[32][16*NT] = [relu](A[32][8*KT] @ B).  A in shared (stride SLDA),
// B in global row-major (ldb), C in shared (stride SLDA).
// All A fragments are loaded before any store -> in-place layers are safe.
template <int KT, int NT, bool RELU>
__device__ __forceinline__ void mlp_layer(const float* A, const float* B,
                                          int ldb, float* C)
{
    wmma::fragment<wmma::matrix_a, 16, 16, 8, wmma::precision::tf32,
                   wmma::row_major> a[2][KT];
    #pragma unroll
    for (int m = 0; m < 2; m++)
        #pragma unroll
        for (int k = 0; k < KT; k++) {
            wmma::load_matrix_sync(a[m][k], A + 16 * m * SLDA + 8 * k, SLDA);
            #pragma unroll
            for (int i = 0; i < a[m][k].num_elements; i++)
                a[m][k].x[i] = wmma::__float_to_tf32(a[m][k].x[i]);
        }

    #pragma unroll
    for (int n = 0; n < NT; n++) {
        wmma::fragment<wmma::accumulator, 16, 16, 8, float> c0, c1;
        wmma::fill_fragment(c0, 0.0f);
        wmma::fill_fragment(c1, 0.0f);
        #pragma unroll
        for (int k = 0; k < KT; k++) {
            wmma::fragment<wmma::matrix_b, 16, 16, 8, wmma::precision::tf32,
                           wmma::row_major> b;
            wmma::load_matrix_sync(b, B + 8 * k * ldb + 16 * n, ldb);
            #pragma unroll
            for (int i = 0; i < b.num_elements; i++)
                b.x[i] = wmma::__float_to_tf32(b.x[i]);
            wmma::mma_sync(c0, a[0][k], b, c0);
            wmma::mma_sync(c1, a[1][k], b, c1);
        }
        if (RELU) {
            #pragma unroll
            for (int i = 0; i < c0.num_elements; i++) {
                c0.x[i] = fmaxf(c0.x[i], 0.0f);
                c1.x[i] = fmaxf(c1.x[i], 0.0f);
            }
        }
        wmma::store_matrix_sync(C + 16 * n, c0, SLDA, wmma::mem_row_major);
        wmma::store_matrix_sync(C + 16 * SLDA + 16 * n, c1, SLDA,
                                wmma::mem_row_major);
    }
}

__global__ __launch_bounds__(MBLK, 3)
void nerf_mlp_kernel(const float* __restrict__ dirp,
                     const float* __restrict__ ws1g,
                     const float* __restrict__ wr1g,
                     const float* __restrict__ wr2g,
                     float* __restrict__ out, int N)
{
    extern __shared__ float smem[];   // [4 warps][32][SLDA]

    const int t = threadIdx.x;
    const int w = t >> 5;
    const int lane = t & 31;
    const int p = blockIdx.x * MBLK + t;
    const bool valid = p < N;

    float* buf = smem + w * (32 * SLDA);
    float* myrow = buf + lane * SLDA;

    // cols [0:32) = enc input
    #pragma unroll
    for (int c = 0; c < 8; c++) {
        float4 v = valid ? g_enc4[c * MAXN + p]
                         : make_float4(0.f, 0.f, 0.f, 0.f);
        *reinterpret_cast<float4*>(myrow + 4 * c) = v;
    }
    __syncwarp();

    // sigma layer 1: [0:32) @ ws1 -> relu -> [32:96)
    mlp_layer<4, 4, true>(buf, ws1g, 64, buf + 32);
    __syncwarp();
    // sigma layer 2: [32:96) @ ws2p -> [96:128)   (g = cols 96..112)
    mlp_layer<8, 2, false>(buf + 32, g_ws2p, 32, buf + 96);
    __syncwarp();

    // epilogue: sigma out; rgb_in = [SH(dir) | geo_feat] into [0:32)
    if (valid) {
        out[3 * N + p] = fmaxf(myrow[96], 0.0f);

        float dx = dirp[3 * p + 0] * 2.0f - 1.0f;
        float dy = dirp[3 * p + 1] * 2.0f - 1.0f;
        float dz = dirp[3 * p + 2] * 2.0f - 1.0f;
        float x2 = dx * dx, y2 = dy * dy, z2 = dz * dz;
        float xy = dx * dy, yz = dy * dz, xz = dx * dz;

        #pragma unroll
        for (int j = 0; j < 16; j++) myrow[16 + j] = myrow[97 + j];

        myrow[0]  = 0.28209479177387814f;
        myrow[1]  = -0.48860251190291987f * dy;
        myrow[2]  = 0.48860251190291987f * dz;
        myrow[3]  = -0.48860251190291987f * dx;
        myrow[4]  = 1.0925484305920792f * xy;
        myrow[5]  = -1.0925484305920792f * yz;
        myrow[6]  = 0.94617469575756f * z2 - 0.31539156525252f;
        myrow[7]  = -1.0925484305920792f * xz;
        myrow[8]  = 0.5462742152960396f * (x2 - y2);
        myrow[9]  = 0.5900435899266435f * dy * (-3.0f * x2 + y2);
        myrow[10] = 2.890611442640554f * xy * dz;
        myrow[11] = 0.4570457994644657f * dy * (1.0f - 5.0f * z2);
        myrow[12] = 0.3731763325901154f * dz * (5.0f * z2 - 3.0f);
        myrow[13] = 0.4570457994644657f * dx * (1.0f - 5.0f * z2);
        myrow[14] = 1.445305721320277f * dz * (x2 - y2);
        myrow[15] = 0.5900435899266435f * dx * (-x2 + 3.0f * y2);
    } else {
        #pragma unroll
        for (int k = 0; k < 32; k++) myrow[k] = 0.0f;
    }
    __syncwarp();

    // rgb layer 1: [0:32) @ wr1 -> relu -> [32:96)
    mlp_layer<4, 4, true>(buf, wr1g, 64, buf + 32);
    __syncwarp();
    // rgb layer 2: [32:96) @ wr2 -> relu -> [32:96) in place
    mlp_layer<8, 4, true>(buf + 32, wr2g, 64, buf + 32);
    __syncwarp();
    // rgb layer 3: [32:96) @ wr3p -> [96:112)
    mlp_layer<8, 1, false>(buf + 32, g_wr3p, 16, buf + 96);
    __syncwarp();

    if (valid) {
        float a0 = myrow[96];
        float a1 = myrow[97];
        float a2 = myrow[98];
        out[3 * p + 0] = 1.0f / (1.0f + __expf(-a0));
        out[3 * p + 1] = 1.0f / (1.0f + __expf(-a1));
        out[3 * p + 2] = 1.0f / (1.0f + __expf(-a2));
    }
}

extern "C" void kernel_launch(void* const* d_in, const int* in_sizes, int n_in,
                              void* d_out, int out_size)
{
    const float* xyz = (const float*)d_in[0];
    const float* dir = (const float*)d_in[1];
    const float* table = (const float*)d_in[2];
    float* out = (float*)d_out;

    int N = in_sizes[0] / 3;

    size_t smem_bytes = (size_t)(4 * 32 * SLDA) * sizeof(float);  // 67.6 KB
    static bool attr_set = false;
    if (!attr_set) {
        cudaFuncSetAttribute(nerf_mlp_kernel,
                             cudaFuncAttributeMaxDynamicSharedMemorySize,
                             (int)smem_bytes);
        attr_set = true;
    }

    pad_weights_kernel<<<8, 256>>>((const float*)d_in[4],
                                   (const float*)d_in[7]);

    int eblocks = (N + EBLK - 1) / EBLK;
    nerf_encode_kernel<<<eblocks, EBLK>>>(xyz, table, N);

    int mblocks = (N + MBLK - 1) / MBLK;
    nerf_mlp_kernel<<<mblocks, MBLK, smem_bytes>>>(
        dir, (const float*)d_in[3], (const float*)d_in[5],
        (const float*)d_in[6], out, N);
}